// round 16
// baseline (speedup 1.0000x reference)
#include <cuda_runtime.h>
#include <cuda_fp16.h>
#include <math.h>
#include <stdint.h>
#include <string.h>

// ---------------------------------------------------------------------------
// FractalBlock on B200 (compute_100 toolchain => no tcgen05).
// fp16 m16n8k16 mma.sync. GEMMs: 128x64 tile (4 CTA/SM) for wide-N,
// 64x64 tile (5 CTA/SM) for N=768 (proj/mlp2) to fill the chip.
// Fused attention (16 q-rows/CTA, 2 CTAs/SM), PV split-key warp layout.
// out [4,1024,768] fp32, attn0/attn1 [4,12,1024,1024] fp32.
// ---------------------------------------------------------------------------

#define B_    4
#define NSEQ  1024
#define DIM_  768
#define HEADS 12
#define HDIM  64
#define MLPH  3072
#define MROWS (B_ * NSEQ)                       // 4096
#define OUT_ELEMS   (MROWS * DIM_)              // 3145728
#define ATTN_ELEMS  (B_ * HEADS * NSEQ * NSEQ)  // 50331648

// Scratch (device globals)
__device__ __half g_ln [MROWS * DIM_];
__device__ __half g_qkv[MROWS * 3 * DIM_];
__device__ __half g_ao [MROWS * DIM_];
__device__ __half g_h  [MROWS * MLPH];
__device__ float  g_x1 [MROWS * DIM_];
__device__ float  g_x2 [MROWS * DIM_];
__device__ float  g_x3 [MROWS * DIM_];
#define WL_STRIDE 7077888
__device__ __half g_wc [2 * WL_STRIDE];

__device__ __forceinline__ float gelu_exact(float x) {
    return 0.5f * x * (1.0f + erff(x * 0.70710678118654752f));
}
__device__ __forceinline__ uint32_t h2_u32(__half2 h) {
    uint32_t u; memcpy(&u, &h, 4); return u;
}
// fp16 mma, f32 accumulate
__device__ __forceinline__ void mma_h(float d[4], uint32_t a0, uint32_t a1,
                                      uint32_t a2, uint32_t a3,
                                      uint32_t b0, uint32_t b1) {
    asm volatile(
        "mma.sync.aligned.m16n8k16.row.col.f32.f16.f16.f32 "
        "{%0,%1,%2,%3},{%4,%5,%6,%7},{%8,%9},{%0,%1,%2,%3};"
        : "+f"(d[0]), "+f"(d[1]), "+f"(d[2]), "+f"(d[3])
        : "r"(a0), "r"(a1), "r"(a2), "r"(a3), "r"(b0), "r"(b1));
}
__device__ __forceinline__ uint32_t smem_u32(const void* p) {
    return (uint32_t)__cvta_generic_to_shared(p);
}
#define CP16(dst, src) asm volatile("cp.async.cg.shared.global [%0],[%1],16;" :: "r"(dst), "l"(src))
#define CP_COMMIT()    asm volatile("cp.async.commit_group;")
#define CP_WAIT1()     asm volatile("cp.async.wait_group 1;")
#define CP_WAIT0()     asm volatile("cp.async.wait_group 0;")

// ldmatrix
#define LDSM4(r, a)                                                           \
    asm volatile("ldmatrix.sync.aligned.m8n8.x4.shared.b16 {%0,%1,%2,%3},[%4];" \
        : "=r"((r)[0]), "=r"((r)[1]), "=r"((r)[2]), "=r"((r)[3]) : "r"(a))
#define LDSM4T(r, a)                                                          \
    asm volatile("ldmatrix.sync.aligned.m8n8.x4.trans.shared.b16 {%0,%1,%2,%3},[%4];" \
        : "=r"((r)[0]), "=r"((r)[1]), "=r"((r)[2]), "=r"((r)[3]) : "r"(a))

// ---------------------------------------------------------------------------
// Batched weight fp16 convert for one layer: 4 segments, contiguous dst.
// ---------------------------------------------------------------------------
__global__ void conv_w4(const float* __restrict__ s0, const float* __restrict__ s1,
                        const float* __restrict__ s2, const float* __restrict__ s3,
                        __half* __restrict__ dst) {
    int blk = blockIdx.x;
    const float* src; int base;
    if (blk < 1728)      { src = s0; base = 0; }
    else if (blk < 2304) { src = s1; base = 1728; }
    else if (blk < 4608) { src = s2; base = 2304; }
    else                 { src = s3; base = 4608; }
    int i = (blk - base) * 256 + threadIdx.x;
    float4 v = ((const float4*)src)[i];
    __half2 h0 = __floats2half2_rn(v.x, v.y);
    __half2 h1 = __floats2half2_rn(v.z, v.w);
    uint2 o = {h2_u32(h0), h2_u32(h1)};
    ((uint2*)dst)[blk * 256 + threadIdx.x] = o;
}

// ---------------------------------------------------------------------------
// LayerNorm: fp32 in -> fp16 out
// ---------------------------------------------------------------------------
__global__ void ln_kernel(const float* __restrict__ x, const float* __restrict__ g,
                          const float* __restrict__ beta, __half* __restrict__ y) {
    int row = blockIdx.x, t = threadIdx.x;
    const float* xr = x + (size_t)row * DIM_;
    float v0 = xr[t], v1 = xr[t + 256], v2 = xr[t + 512];
    float s = v0 + v1 + v2;
    float q = v0 * v0 + v1 * v1 + v2 * v2;
    __shared__ float rs[8], rq[8];
    #pragma unroll
    for (int o = 16; o; o >>= 1) {
        s += __shfl_xor_sync(0xffffffffu, s, o);
        q += __shfl_xor_sync(0xffffffffu, q, o);
    }
    int lane = t & 31, w = t >> 5;
    if (!lane) { rs[w] = s; rq[w] = q; }
    __syncthreads();
    float S = 0.f, Q = 0.f;
    #pragma unroll
    for (int i = 0; i < 8; ++i) { S += rs[i]; Q += rq[i]; }
    float mean = S * (1.0f / DIM_);
    float var  = Q * (1.0f / DIM_) - mean * mean;
    float inv  = rsqrtf(var + 1e-5f);
    __half* yr = y + (size_t)row * DIM_;
    yr[t]       = __float2half_rn((v0 - mean) * inv * g[t]       + beta[t]);
    yr[t + 256] = __float2half_rn((v1 - mean) * inv * g[t + 256] + beta[t + 256]);
    yr[t + 512] = __float2half_rn((v2 - mean) * inv * g[t + 512] + beta[t + 512]);
}

// ---------------------------------------------------------------------------
// LN of blend: xb = 0.5*(a+b) (written fp32), y = LN(xb) (half)
// ---------------------------------------------------------------------------
__global__ void ln_blend_kernel(const float* __restrict__ a, const float* __restrict__ bsrc,
                                const float* __restrict__ g, const float* __restrict__ beta,
                                __half* __restrict__ y, float* __restrict__ xb) {
    int row = blockIdx.x, t = threadIdx.x;
    const float* ar = a + (size_t)row * DIM_;
    const float* br = bsrc + (size_t)row * DIM_;
    float v0 = 0.5f * (ar[t] + br[t]);
    float v1 = 0.5f * (ar[t + 256] + br[t + 256]);
    float v2 = 0.5f * (ar[t + 512] + br[t + 512]);
    float* xr = xb + (size_t)row * DIM_;
    xr[t] = v0; xr[t + 256] = v1; xr[t + 512] = v2;
    float s = v0 + v1 + v2;
    float q = v0 * v0 + v1 * v1 + v2 * v2;
    __shared__ float rs[8], rq[8];
    #pragma unroll
    for (int o = 16; o; o >>= 1) {
        s += __shfl_xor_sync(0xffffffffu, s, o);
        q += __shfl_xor_sync(0xffffffffu, q, o);
    }
    int lane = t & 31, w = t >> 5;
    if (!lane) { rs[w] = s; rq[w] = q; }
    __syncthreads();
    float S = 0.f, Q = 0.f;
    #pragma unroll
    for (int i = 0; i < 8; ++i) { S += rs[i]; Q += rq[i]; }
    float mean = S * (1.0f / DIM_);
    float var  = Q * (1.0f / DIM_) - mean * mean;
    float inv  = rsqrtf(var + 1e-5f);
    __half* yr = y + (size_t)row * DIM_;
    yr[t]       = __float2half_rn((v0 - mean) * inv * g[t]       + beta[t]);
    yr[t + 256] = __float2half_rn((v1 - mean) * inv * g[t + 256] + beta[t + 256]);
    yr[t + 512] = __float2half_rn((v2 - mean) * inv * g[t + 512] + beta[t + 512]);
}

// ---------------------------------------------------------------------------
// fp16 GEMM (wide-N): C[M,N] = A[M,K] @ W[K,N] + bias (+res | +gelu)
// CTA tile 128x64, BK=32, 8 warps 4x2, 3-stage cp.async, 4 CTAs/SM.
// ---------------------------------------------------------------------------
#define HST 40     // A smem row stride (halves)
#define BNST 72    // B smem row stride (halves)
#define GSTG 3
#define A_STAGE (128 * HST)
#define B_STAGE (32 * BNST)
#define GEMM_SMEM ((GSTG * A_STAGE + GSTG * B_STAGE) * 2)   // 44544 B

template<int EPI>
__global__ void __launch_bounds__(256, 4)
gemm_h(const __half* __restrict__ A, const __half* __restrict__ W,
       const float* __restrict__ bias, const float* __restrict__ R,
       void* __restrict__ Cv, int M, int N, int K) {
    extern __shared__ __half sm[];
    __half* As = sm;
    __half* Bs = sm + GSTG * A_STAGE;
    const int t = threadIdx.x;
    const int w = t >> 5, lane = t & 31, g = lane >> 2, c = lane & 3;
    const int wm = (w >> 1) * 32, wn = (w & 1) * 32;
    const int m0 = blockIdx.y * 128, n0 = blockIdx.x * 64;
    const int NT = K / 32;
    const int lrow = lane & 15;
    const int lcolA = (lane >> 4) * 8;

    auto issue = [&](int kt, int s) {
        __half* Ad = As + s * A_STAGE;
        __half* Bd = Bs + s * B_STAGE;
        #pragma unroll
        for (int i = 0; i < 2; ++i) {
            int li = t + i * 256;
            int arow = li >> 2, ach = li & 3;
            CP16(smem_u32(Ad + arow * HST + ach * 8),
                 A + (size_t)(m0 + arow) * K + kt * 32 + ach * 8);
        }
        {
            int brow = t >> 3, bch = t & 7;
            CP16(smem_u32(Bd + brow * BNST + bch * 8),
                 W + (size_t)(kt * 32 + brow) * N + n0 + bch * 8);
        }
        CP_COMMIT();
    };

    issue(0, 0);
    if (NT > 1) issue(1, 1);
    float acc[2][4][4] = {};
    for (int kt = 0; kt < NT; ++kt) {
        int s = kt % GSTG;
        if (kt + 1 < NT) CP_WAIT1(); else CP_WAIT0();
        __syncthreads();
        const __half* Asb = As + s * A_STAGE;
        const __half* Bsb = Bs + s * B_STAGE;
        #pragma unroll
        for (int ks = 0; ks < 2; ++ks) {
            const int k16 = ks * 16;
            uint32_t af[2][4], bf[2][4];
            #pragma unroll
            for (int mt = 0; mt < 2; ++mt)
                LDSM4(af[mt], smem_u32(Asb + (wm + mt * 16 + lrow) * HST + k16 + lcolA));
            #pragma unroll
            for (int np = 0; np < 2; ++np)
                LDSM4T(bf[np], smem_u32(Bsb + (k16 + lrow) * BNST + wn + np * 16 + lcolA));
            #pragma unroll
            for (int mt = 0; mt < 2; ++mt)
                #pragma unroll
                for (int np = 0; np < 2; ++np) {
                    mma_h(acc[mt][np * 2 + 0], af[mt][0], af[mt][1], af[mt][2], af[mt][3],
                          bf[np][0], bf[np][1]);
                    mma_h(acc[mt][np * 2 + 1], af[mt][0], af[mt][1], af[mt][2], af[mt][3],
                          bf[np][2], bf[np][3]);
                }
        }
        if (kt + 2 < NT) issue(kt + 2, (kt + 2) % GSTG);
    }

    #pragma unroll
    for (int mt = 0; mt < 2; ++mt) {
        #pragma unroll
        for (int nt = 0; nt < 4; ++nt) {
            int row = m0 + wm + mt * 16 + g;
            int col = n0 + wn + nt * 8 + 2 * c;
            float2 bb = *(const float2*)&bias[col];
            #pragma unroll
            for (int hh = 0; hh < 2; ++hh) {
                size_t idx = (size_t)(row + hh * 8) * N + col;
                float v0 = acc[mt][nt][hh * 2 + 0] + bb.x;
                float v1 = acc[mt][nt][hh * 2 + 1] + bb.y;
                if (EPI == 1) {
                    float2 rr = *(const float2*)&R[idx];
                    float2 o = {v0 + rr.x, v1 + rr.y};
                    *(float2*)&((float*)Cv)[idx] = o;
                } else {
                    if (EPI == 2) { v0 = gelu_exact(v0); v1 = gelu_exact(v1); }
                    __half2 o = __halves2half2(__float2half_rn(v0), __float2half_rn(v1));
                    *(__half2*)&((__half*)Cv)[idx] = o;
                }
            }
        }
    }
}

// ---------------------------------------------------------------------------
// fp16 GEMM (narrow-N, N=768): CTA tile 64x64, 8 warps 2x4 (warp 32x16),
// 3-stage cp.async, 5 CTAs/SM. Doubles grid to fill the chip.
// ---------------------------------------------------------------------------
#define A64_STAGE (64 * HST)      // 2560 halves
#define GEMM64_SMEM ((GSTG * A64_STAGE + GSTG * B_STAGE) * 2)   // 29184 B

template<int EPI>
__global__ void __launch_bounds__(256, 5)
gemm_h64(const __half* __restrict__ A, const __half* __restrict__ W,
         const float* __restrict__ bias, const float* __restrict__ R,
         void* __restrict__ Cv, int M, int N, int K) {
    extern __shared__ __half sm[];
    __half* As = sm;                        // [GSTG][64][HST]
    __half* Bs = sm + GSTG * A64_STAGE;     // [GSTG][32][BNST]
    const int t = threadIdx.x;
    const int w = t >> 5, lane = t & 31, g = lane >> 2, c = lane & 3;
    const int wm = (w >> 2) * 32, wn = (w & 3) * 16;
    const int m0 = blockIdx.y * 64, n0 = blockIdx.x * 64;
    const int NT = K / 32;
    const int lrow = lane & 15;
    const int lcolA = (lane >> 4) * 8;

    auto issue = [&](int kt, int s) {
        __half* Ad = As + s * A64_STAGE;
        __half* Bd = Bs + s * B_STAGE;
        {   // A: 64 rows x 4 chunks = 256
            int arow = t >> 2, ach = t & 3;
            CP16(smem_u32(Ad + arow * HST + ach * 8),
                 A + (size_t)(m0 + arow) * K + kt * 32 + ach * 8);
        }
        {   // B: 32 rows x 8 chunks = 256
            int brow = t >> 3, bch = t & 7;
            CP16(smem_u32(Bd + brow * BNST + bch * 8),
                 W + (size_t)(kt * 32 + brow) * N + n0 + bch * 8);
        }
        CP_COMMIT();
    };

    issue(0, 0);
    if (NT > 1) issue(1, 1);
    float acc[2][2][4] = {};
    for (int kt = 0; kt < NT; ++kt) {
        int s = kt % GSTG;
        if (kt + 1 < NT) CP_WAIT1(); else CP_WAIT0();
        __syncthreads();
        const __half* Asb = As + s * A64_STAGE;
        const __half* Bsb = Bs + s * B_STAGE;
        #pragma unroll
        for (int ks = 0; ks < 2; ++ks) {
            const int k16 = ks * 16;
            uint32_t af[2][4], bf[4];
            #pragma unroll
            for (int mt = 0; mt < 2; ++mt)
                LDSM4(af[mt], smem_u32(Asb + (wm + mt * 16 + lrow) * HST + k16 + lcolA));
            LDSM4T(bf, smem_u32(Bsb + (k16 + lrow) * BNST + wn + lcolA));
            #pragma unroll
            for (int mt = 0; mt < 2; ++mt) {
                mma_h(acc[mt][0], af[mt][0], af[mt][1], af[mt][2], af[mt][3], bf[0], bf[1]);
                mma_h(acc[mt][1], af[mt][0], af[mt][1], af[mt][2], af[mt][3], bf[2], bf[3]);
            }
        }
        if (kt + 2 < NT) issue(kt + 2, (kt + 2) % GSTG);
    }

    #pragma unroll
    for (int mt = 0; mt < 2; ++mt) {
        #pragma unroll
        for (int nt = 0; nt < 2; ++nt) {
            int row = m0 + wm + mt * 16 + g;
            int col = n0 + wn + nt * 8 + 2 * c;
            float2 bb = *(const float2*)&bias[col];
            #pragma unroll
            for (int hh = 0; hh < 2; ++hh) {
                size_t idx = (size_t)(row + hh * 8) * N + col;
                float v0 = acc[mt][nt][hh * 2 + 0] + bb.x;
                float v1 = acc[mt][nt][hh * 2 + 1] + bb.y;
                if (EPI == 1) {
                    float2 rr = *(const float2*)&R[idx];
                    float2 o = {v0 + rr.x, v1 + rr.y};
                    *(float2*)&((float*)Cv)[idx] = o;
                } else {
                    if (EPI == 2) { v0 = gelu_exact(v0); v1 = gelu_exact(v1); }
                    __half2 o = __halves2half2(__float2half_rn(v0), __float2half_rn(v1));
                    *(__half2*)&((__half*)Cv)[idx] = o;
                }
            }
        }
    }
}

// ---------------------------------------------------------------------------
// Fused attention: scores + softmax + attn-map write + PV, 16 q-rows per CTA.
// Phase 1: 8 warps x 16 keys. Phase 3 (PV): warp = d-group x key-half,
// partials reduced through smem. 105.5 KB smem -> 2 CTAs/SM.
// ---------------------------------------------------------------------------
#define SMST 1036
#define SMSTH (2 * SMST)
#define QST  72
#define SC_SMEM (16*SMST*4 + 16*QST*2 + 2*128*QST*2)   // 105472

__global__ void attn_fused(const __half* __restrict__ qkv, float* __restrict__ S,
                           __half* __restrict__ O) {
    extern __shared__ char smraw[];
    float*  Sm = (float*)smraw;
    __half* SmH = (__half*)smraw;
    __half* Qs = (__half*)(smraw + 16 * SMST * 4);
    __half* KV = Qs + 16 * QST;
    const int t = threadIdx.x;
    const int w = t >> 5, lane = t & 31, g = lane >> 2, c = lane & 3;
    const int bh = blockIdx.y, b = bh / HEADS, h = bh % HEADS;
    const int m0 = blockIdx.x * 16;
    const int wn16 = w * 16;
    const int dg  = (w & 3) * 16;
    const int kh  = w >> 2;
    const __half* Qb = qkv + ((size_t)b * NSEQ + m0) * (3 * DIM_) + h * HDIM;
    const __half* Kb = qkv + ((size_t)b * NSEQ) * (3 * DIM_) + DIM_ + h * HDIM;
    const __half* Vb = qkv + ((size_t)b * NSEQ) * (3 * DIM_) + 2 * DIM_ + h * HDIM;
    const int lrow = lane & 15;
    const int lcolA = (lane >> 4) * 8;
    const int browB = (lane >> 4) * 8 + (lane & 7);
    const int bcolB = lane & 8;

    if (t < 128) {
        int row = t >> 3, ch = t & 7;
        CP16(smem_u32(&Qs[row * QST + ch * 8]),
             Qb + (size_t)row * (3 * DIM_) + ch * 8);
    }
    CP_COMMIT();

    auto issueKV = [&](const __half* base, int chn, int buf) {
        __half* Kd = KV + buf * 128 * QST;
        const __half* Kg = base + (size_t)(chn * 128) * (3 * DIM_);
        #pragma unroll
        for (int i = 0; i < 4; ++i) {
            int li = t + i * 256;
            int key = li >> 3, ch = li & 7;
            CP16(smem_u32(&Kd[key * QST + ch * 8]),
                 Kg + (size_t)key * (3 * DIM_) + ch * 8);
        }
        CP_COMMIT();
    };
    issueKV(Kb, 0, 0);
    CP_WAIT0();
    __syncthreads();

    uint32_t aq[4][4];
    #pragma unroll
    for (int ks = 0; ks < 4; ++ks)
        LDSM4(aq[ks], smem_u32(&Qs[lrow * QST + ks * 16 + lcolA]));

    // ---- Phase 1: scores ----
    for (int chn = 0; chn < 8; ++chn) {
        int buf = chn & 1;
        if (chn + 1 < 8) { issueKV(Kb, chn + 1, buf ^ 1); CP_WAIT1(); }
        else             { CP_WAIT0(); }
        __syncthreads();
        const __half* Kc = KV + buf * 128 * QST;
        float acc[2][4] = {};
        #pragma unroll
        for (int ks = 0; ks < 4; ++ks) {
            uint32_t bf[4];
            LDSM4(bf, smem_u32(&Kc[(wn16 + browB) * QST + ks * 16 + bcolB]));
            mma_h(acc[0], aq[ks][0], aq[ks][1], aq[ks][2], aq[ks][3], bf[0], bf[1]);
            mma_h(acc[1], aq[ks][0], aq[ks][1], aq[ks][2], aq[ks][3], bf[2], bf[3]);
        }
        const float scl = 0.125f;
        #pragma unroll
        for (int nt = 0; nt < 2; ++nt) {
            int colb = chn * 128 + wn16 + nt * 8 + 2 * c;
            float2 o0 = {acc[nt][0] * scl, acc[nt][1] * scl};
            float2 o1 = {acc[nt][2] * scl, acc[nt][3] * scl};
            *(float2*)&Sm[g * SMST + colb]       = o0;
            *(float2*)&Sm[(g + 8) * SMST + colb] = o1;
        }
        __syncthreads();
    }

    issueKV(Vb, 0, 0);
    issueKV(Vb, 1, 1);

    // ---- Phase 2: softmax; fp32 map + half P in place ----
    #pragma unroll
    for (int i = 0; i < 2; ++i) {
        int r = w * 2 + i;
        const float* rowp = Sm + r * SMST;
        __half* hrow = SmH + r * SMSTH;
        float4 v[8];
        float mx = -INFINITY;
        #pragma unroll
        for (int j = 0; j < 8; ++j) {
            v[j] = *(const float4*)(rowp + lane * 4 + j * 128);
            mx = fmaxf(mx, fmaxf(fmaxf(v[j].x, v[j].y), fmaxf(v[j].z, v[j].w)));
        }
        #pragma unroll
        for (int o = 16; o; o >>= 1) mx = fmaxf(mx, __shfl_xor_sync(0xffffffffu, mx, o));
        float s = 0.f;
        #pragma unroll
        for (int j = 0; j < 8; ++j) {
            v[j].x = __expf(v[j].x - mx); v[j].y = __expf(v[j].y - mx);
            v[j].z = __expf(v[j].z - mx); v[j].w = __expf(v[j].w - mx);
            s += v[j].x + v[j].y + v[j].z + v[j].w;
        }
        #pragma unroll
        for (int o = 16; o; o >>= 1) s += __shfl_xor_sync(0xffffffffu, s, o);
        float inv = 1.0f / s;
        float* outp = S + ((size_t)bh * NSEQ + m0 + r) * NSEQ + lane * 4;
        #pragma unroll
        for (int j = 0; j < 8; ++j) {
            float4 o = {v[j].x * inv, v[j].y * inv, v[j].z * inv, v[j].w * inv};
            *(float4*)(outp + j * 128) = o;
            __half2 h0 = __floats2half2_rn(o.x, o.y);
            __half2 h1 = __floats2half2_rn(o.z, o.w);
            uint2 hp = {h2_u32(h0), h2_u32(h1)};
            *(uint2*)(hrow + lane * 4 + j * 128) = hp;
        }
    }

    // ---- Phase 3: PV (warp = 16 rows x 16 d-cols over its 64-key half) ----
    float acc2[2][4] = {};
    for (int chn = 0; chn < 8; ++chn) {
        int buf = chn & 1;
        if (chn + 2 < 8) CP_WAIT1(); else CP_WAIT0();
        __syncthreads();
        const __half* Vc = KV + buf * 128 * QST;
        #pragma unroll
        for (int ks = 0; ks < 4; ++ks) {
            const int kk = kh * 64 + ks * 16;
            uint32_t pf[4], vf[4];
            LDSM4(pf, smem_u32(&SmH[lrow * SMSTH + chn * 128 + kk + lcolA]));
            LDSM4T(vf, smem_u32(&Vc[(kk + lrow) * QST + dg + lcolA]));
            mma_h(acc2[0], pf[0], pf[1], pf[2], pf[3], vf[0], vf[1]);
            mma_h(acc2[1], pf[0], pf[1], pf[2], pf[3], vf[2], vf[3]);
        }
        __syncthreads();
        if (chn + 2 < 8) issueKV(Vb, chn + 2, buf);
    }

    // Reduce key halves via Sm (free now).
    __syncthreads();
    float* red = Sm;
    if (kh == 1) {
        float* dst = red + ((w & 3) * 32 + lane) * 8;
        #pragma unroll
        for (int nt = 0; nt < 2; ++nt)
            #pragma unroll
            for (int i = 0; i < 4; ++i) dst[nt * 4 + i] = acc2[nt][i];
    }
    __syncthreads();
    if (kh == 0) {
        const float* src = red + ((w & 3) * 32 + lane) * 8;
        #pragma unroll
        for (int nt = 0; nt < 2; ++nt)
            #pragma unroll
            for (int i = 0; i < 4; ++i) acc2[nt][i] += src[nt * 4 + i];
        #pragma unroll
        for (int nt = 0; nt < 2; ++nt) {
            int col = dg + nt * 8 + 2 * c;
            #pragma unroll
            for (int hh = 0; hh < 2; ++hh) {
                int row = m0 + g + hh * 8;
                size_t idx = ((size_t)b * NSEQ + row) * DIM_ + h * HDIM + col;
                __half2 o = __halves2half2(__float2half_rn(acc2[nt][hh * 2 + 0]),
                                           __float2half_rn(acc2[nt][hh * 2 + 1]));
                *(__half2*)&O[idx] = o;
            }
        }
    }
}

// ---------------------------------------------------------------------------
// Host orchestration
// ---------------------------------------------------------------------------
extern "C" void kernel_launch(void* const* d_in, const int* in_sizes, int n_in,
                              void* d_out, int out_size) {
    (void)in_sizes; (void)n_in; (void)out_size;
    const float* x = (const float*)d_in[0];
    const float* prm[24];
    for (int i = 0; i < 24; ++i) prm[i] = (const float*)d_in[1 + i];
    // per-layer: 0 qkv_w, 1 qkv_b, 2 proj_w, 3 proj_b, 4 ln1_g, 5 ln1_b,
    //            6 ln2_g, 7 ln2_b, 8 mlp_w1, 9 mlp_b1, 10 mlp_w2, 11 mlp_b2

    float* out   = (float*)d_out;
    float* attn0 = out + OUT_ELEMS;
    float* attn1 = attn0 + ATTN_ELEMS;

    __half *p_ln, *p_qkv, *p_ao, *p_h, *p_wc;
    float *p_x1, *p_x2, *p_x3;
    cudaGetSymbolAddress((void**)&p_ln,  g_ln);
    cudaGetSymbolAddress((void**)&p_qkv, g_qkv);
    cudaGetSymbolAddress((void**)&p_ao,  g_ao);
    cudaGetSymbolAddress((void**)&p_h,   g_h);
    cudaGetSymbolAddress((void**)&p_x1,  g_x1);
    cudaGetSymbolAddress((void**)&p_x2,  g_x2);
    cudaGetSymbolAddress((void**)&p_x3,  g_x3);
    cudaGetSymbolAddress((void**)&p_wc,  g_wc);

    cudaFuncSetAttribute(attn_fused,
                         cudaFuncAttributeMaxDynamicSharedMemorySize, SC_SMEM);
    cudaFuncSetAttribute(gemm_h<0>, cudaFuncAttributeMaxDynamicSharedMemorySize, GEMM_SMEM);
    cudaFuncSetAttribute(gemm_h<1>, cudaFuncAttributeMaxDynamicSharedMemorySize, GEMM_SMEM);
    cudaFuncSetAttribute(gemm_h<2>, cudaFuncAttributeMaxDynamicSharedMemorySize, GEMM_SMEM);
    cudaFuncSetAttribute(gemm_h64<1>, cudaFuncAttributeMaxDynamicSharedMemorySize, GEMM64_SMEM);

    dim3 blk(256);

    const int QKV_N = DIM_ * 3 * DIM_;
    const int PRJ_N = DIM_ * DIM_;
    const int W1_N  = DIM_ * MLPH;
    __half* wq[2]; __half* wp[2]; __half* w1[2]; __half* w2[2];
    for (int L = 0; L < 2; ++L) {
        __half* base = p_wc + (size_t)L * WL_STRIDE;
        wq[L] = base;
        wp[L] = base + QKV_N;
        w1[L] = base + QKV_N + PRJ_N;
        w2[L] = base + QKV_N + PRJ_N + W1_N;
        conv_w4<<<WL_STRIDE / 1024, blk>>>(prm[L*12 + 0], prm[L*12 + 2],
                                           prm[L*12 + 8], prm[L*12 + 10], base);
    }

    auto attention = [&](int L, const float* xin, float* attnbuf, float* xout) {
        const float* const* p = prm + L * 12;
        ln_kernel<<<MROWS, blk>>>(xin, p[4], p[5], p_ln);
        gemm_h<0><<<dim3(3 * DIM_ / 64, MROWS / 128), blk, GEMM_SMEM>>>(
            p_ln, wq[L], p[1], nullptr, p_qkv, MROWS, 3 * DIM_, DIM_);
        attn_fused<<<dim3(NSEQ / 16, 48), blk, SC_SMEM>>>(p_qkv, attnbuf, p_ao);
        gemm_h64<1><<<dim3(DIM_ / 64, MROWS / 64), blk, GEMM64_SMEM>>>(
            p_ao, wp[L], p[3], xin, xout, MROWS, DIM_, DIM_);
    };
    auto mlp_tail = [&](int L, const __half* lnin, const float* resid, float* xout) {
        const float* const* p = prm + L * 12;
        gemm_h<2><<<dim3(MLPH / 64, MROWS / 128), blk, GEMM_SMEM>>>(
            lnin, w1[L], p[9], nullptr, p_h, MROWS, MLPH, DIM_);
        gemm_h64<1><<<dim3(DIM_ / 64, MROWS / 64), blk, GEMM64_SMEM>>>(
            p_h, w2[L], p[11], resid, xout, MROWS, DIM_, MLPH);
    };

    attention(0, x,    attn0, p_x1);
    attention(1, p_x1, attn1, p_x2);
    ln_kernel<<<MROWS, blk>>>(p_x2, prm[12 + 6], prm[12 + 7], p_ln);
    mlp_tail(1, p_ln, p_x2, p_x3);
    ln_blend_kernel<<<MROWS, blk>>>(p_x1, p_x3, prm[6], prm[7], p_ln, p_x2);
    mlp_tail(0, p_ln, p_x2, out);
}

// round 17
// speedup vs baseline: 1.0811x; 1.0811x over previous
#include <cuda_runtime.h>
#include <cuda_fp16.h>
#include <math.h>
#include <stdint.h>
#include <string.h>

// ---------------------------------------------------------------------------
// FractalBlock on B200 (compute_100 toolchain => no tcgen05).
// fp16 m16n8k16 mma.sync; GEMM 128x64 tile, 3-stage cp.async, 4 CTAs/SM.
// Fused attention (16 q-rows/CTA, 2 CTAs/SM), PV split-key warp layout.
// Single batched weight-conversion launch.
// out [4,1024,768] fp32, attn0/attn1 [4,12,1024,1024] fp32.
// ---------------------------------------------------------------------------

#define B_    4
#define NSEQ  1024
#define DIM_  768
#define HEADS 12
#define HDIM  64
#define MLPH  3072
#define MROWS (B_ * NSEQ)                       // 4096
#define OUT_ELEMS   (MROWS * DIM_)              // 3145728
#define ATTN_ELEMS  (B_ * HEADS * NSEQ * NSEQ)  // 50331648

// Scratch (device globals)
__device__ __half g_ln [MROWS * DIM_];
__device__ __half g_qkv[MROWS * 3 * DIM_];
__device__ __half g_ao [MROWS * DIM_];
__device__ __half g_h  [MROWS * MLPH];
__device__ float  g_x1 [MROWS * DIM_];
__device__ float  g_x2 [MROWS * DIM_];
__device__ float  g_x3 [MROWS * DIM_];
#define WL_STRIDE 7077888   // = 6912 * 1024 halves per layer
__device__ __half g_wc [2 * WL_STRIDE];

__device__ __forceinline__ float gelu_exact(float x) {
    return 0.5f * x * (1.0f + erff(x * 0.70710678118654752f));
}
__device__ __forceinline__ uint32_t h2_u32(__half2 h) {
    uint32_t u; memcpy(&u, &h, 4); return u;
}
// fp16 mma, f32 accumulate
__device__ __forceinline__ void mma_h(float d[4], uint32_t a0, uint32_t a1,
                                      uint32_t a2, uint32_t a3,
                                      uint32_t b0, uint32_t b1) {
    asm volatile(
        "mma.sync.aligned.m16n8k16.row.col.f32.f16.f16.f32 "
        "{%0,%1,%2,%3},{%4,%5,%6,%7},{%8,%9},{%0,%1,%2,%3};"
        : "+f"(d[0]), "+f"(d[1]), "+f"(d[2]), "+f"(d[3])
        : "r"(a0), "r"(a1), "r"(a2), "r"(a3), "r"(b0), "r"(b1));
}
__device__ __forceinline__ uint32_t smem_u32(const void* p) {
    return (uint32_t)__cvta_generic_to_shared(p);
}
#define CP16(dst, src) asm volatile("cp.async.cg.shared.global [%0],[%1],16;" :: "r"(dst), "l"(src))
#define CP_COMMIT()    asm volatile("cp.async.commit_group;")
#define CP_WAIT1()     asm volatile("cp.async.wait_group 1;")
#define CP_WAIT0()     asm volatile("cp.async.wait_group 0;")

// ldmatrix
#define LDSM4(r, a)                                                           \
    asm volatile("ldmatrix.sync.aligned.m8n8.x4.shared.b16 {%0,%1,%2,%3},[%4];" \
        : "=r"((r)[0]), "=r"((r)[1]), "=r"((r)[2]), "=r"((r)[3]) : "r"(a))
#define LDSM4T(r, a)                                                          \
    asm volatile("ldmatrix.sync.aligned.m8n8.x4.trans.shared.b16 {%0,%1,%2,%3},[%4];" \
        : "=r"((r)[0]), "=r"((r)[1]), "=r"((r)[2]), "=r"((r)[3]) : "r"(a))

// ---------------------------------------------------------------------------
// Batched weight fp16 convert, BOTH layers in one launch.
// Per-layer block boundaries (1024 elems/block): 1728 / 576 / 2304 / 2304 = 6912.
// dst (g_wc) is contiguous across segments and layers.
// ---------------------------------------------------------------------------
__global__ void conv_w8(const float* __restrict__ a0, const float* __restrict__ a1,
                        const float* __restrict__ a2, const float* __restrict__ a3,
                        const float* __restrict__ b0, const float* __restrict__ b1,
                        const float* __restrict__ b2, const float* __restrict__ b3,
                        __half* __restrict__ dst) {
    int blk = blockIdx.x;
    int r = blk % 6912;
    const float* src; int base;
    if (blk < 6912) {
        if (r < 1728)      { src = a0; base = 0; }
        else if (r < 2304) { src = a1; base = 1728; }
        else if (r < 4608) { src = a2; base = 2304; }
        else               { src = a3; base = 4608; }
    } else {
        if (r < 1728)      { src = b0; base = 0; }
        else if (r < 2304) { src = b1; base = 1728; }
        else if (r < 4608) { src = b2; base = 2304; }
        else               { src = b3; base = 4608; }
    }
    int i = (r - base) * 256 + threadIdx.x;
    float4 v = ((const float4*)src)[i];
    __half2 h0 = __floats2half2_rn(v.x, v.y);
    __half2 h1 = __floats2half2_rn(v.z, v.w);
    uint2 o = {h2_u32(h0), h2_u32(h1)};
    ((uint2*)dst)[blk * 256 + threadIdx.x] = o;
}

// ---------------------------------------------------------------------------
// LayerNorm: fp32 in -> fp16 out
// ---------------------------------------------------------------------------
__global__ void ln_kernel(const float* __restrict__ x, const float* __restrict__ g,
                          const float* __restrict__ beta, __half* __restrict__ y) {
    int row = blockIdx.x, t = threadIdx.x;
    const float* xr = x + (size_t)row * DIM_;
    float v0 = xr[t], v1 = xr[t + 256], v2 = xr[t + 512];
    float s = v0 + v1 + v2;
    float q = v0 * v0 + v1 * v1 + v2 * v2;
    __shared__ float rs[8], rq[8];
    #pragma unroll
    for (int o = 16; o; o >>= 1) {
        s += __shfl_xor_sync(0xffffffffu, s, o);
        q += __shfl_xor_sync(0xffffffffu, q, o);
    }
    int lane = t & 31, w = t >> 5;
    if (!lane) { rs[w] = s; rq[w] = q; }
    __syncthreads();
    float S = 0.f, Q = 0.f;
    #pragma unroll
    for (int i = 0; i < 8; ++i) { S += rs[i]; Q += rq[i]; }
    float mean = S * (1.0f / DIM_);
    float var  = Q * (1.0f / DIM_) - mean * mean;
    float inv  = rsqrtf(var + 1e-5f);
    __half* yr = y + (size_t)row * DIM_;
    yr[t]       = __float2half_rn((v0 - mean) * inv * g[t]       + beta[t]);
    yr[t + 256] = __float2half_rn((v1 - mean) * inv * g[t + 256] + beta[t + 256]);
    yr[t + 512] = __float2half_rn((v2 - mean) * inv * g[t + 512] + beta[t + 512]);
}

// ---------------------------------------------------------------------------
// LN of blend: xb = 0.5*(a+b) (written fp32), y = LN(xb) (half)
// ---------------------------------------------------------------------------
__global__ void ln_blend_kernel(const float* __restrict__ a, const float* __restrict__ bsrc,
                                const float* __restrict__ g, const float* __restrict__ beta,
                                __half* __restrict__ y, float* __restrict__ xb) {
    int row = blockIdx.x, t = threadIdx.x;
    const float* ar = a + (size_t)row * DIM_;
    const float* br = bsrc + (size_t)row * DIM_;
    float v0 = 0.5f * (ar[t] + br[t]);
    float v1 = 0.5f * (ar[t + 256] + br[t + 256]);
    float v2 = 0.5f * (ar[t + 512] + br[t + 512]);
    float* xr = xb + (size_t)row * DIM_;
    xr[t] = v0; xr[t + 256] = v1; xr[t + 512] = v2;
    float s = v0 + v1 + v2;
    float q = v0 * v0 + v1 * v1 + v2 * v2;
    __shared__ float rs[8], rq[8];
    #pragma unroll
    for (int o = 16; o; o >>= 1) {
        s += __shfl_xor_sync(0xffffffffu, s, o);
        q += __shfl_xor_sync(0xffffffffu, q, o);
    }
    int lane = t & 31, w = t >> 5;
    if (!lane) { rs[w] = s; rq[w] = q; }
    __syncthreads();
    float S = 0.f, Q = 0.f;
    #pragma unroll
    for (int i = 0; i < 8; ++i) { S += rs[i]; Q += rq[i]; }
    float mean = S * (1.0f / DIM_);
    float var  = Q * (1.0f / DIM_) - mean * mean;
    float inv  = rsqrtf(var + 1e-5f);
    __half* yr = y + (size_t)row * DIM_;
    yr[t]       = __float2half_rn((v0 - mean) * inv * g[t]       + beta[t]);
    yr[t + 256] = __float2half_rn((v1 - mean) * inv * g[t + 256] + beta[t + 256]);
    yr[t + 512] = __float2half_rn((v2 - mean) * inv * g[t + 512] + beta[t + 512]);
}

// ---------------------------------------------------------------------------
// fp16 GEMM: C[M,N] = A[M,K] @ W[K,N] + bias (+res | +gelu)
// CTA tile 128x64, BK=32, 8 warps 4x2, 3-stage cp.async (prefetch dist 2),
// 4 CTAs/SM via __launch_bounds__(256, 4) (<=64 regs).
// EPI: 0 = bias -> half out; 1 = bias+residual -> fp32 out; 2 = bias+gelu -> half out
// ---------------------------------------------------------------------------
#define HST 40     // A smem row stride (halves)
#define BNST 72    // B smem row stride (halves)
#define GSTG 3
#define A_STAGE (128 * HST)
#define B_STAGE (32 * BNST)
#define GEMM_SMEM ((GSTG * A_STAGE + GSTG * B_STAGE) * 2)   // 44544 B

template<int EPI>
__global__ void __launch_bounds__(256, 4)
gemm_h(const __half* __restrict__ A, const __half* __restrict__ W,
       const float* __restrict__ bias, const float* __restrict__ R,
       void* __restrict__ Cv, int M, int N, int K) {
    extern __shared__ __half sm[];
    __half* As = sm;
    __half* Bs = sm + GSTG * A_STAGE;
    const int t = threadIdx.x;
    const int w = t >> 5, lane = t & 31, g = lane >> 2, c = lane & 3;
    const int wm = (w >> 1) * 32, wn = (w & 1) * 32;
    const int m0 = blockIdx.y * 128, n0 = blockIdx.x * 64;
    const int NT = K / 32;
    const int lrow = lane & 15;
    const int lcolA = (lane >> 4) * 8;

    auto issue = [&](int kt, int s) {
        __half* Ad = As + s * A_STAGE;
        __half* Bd = Bs + s * B_STAGE;
        #pragma unroll
        for (int i = 0; i < 2; ++i) {
            int li = t + i * 256;
            int arow = li >> 2, ach = li & 3;
            CP16(smem_u32(Ad + arow * HST + ach * 8),
                 A + (size_t)(m0 + arow) * K + kt * 32 + ach * 8);
        }
        {
            int brow = t >> 3, bch = t & 7;
            CP16(smem_u32(Bd + brow * BNST + bch * 8),
                 W + (size_t)(kt * 32 + brow) * N + n0 + bch * 8);
        }
        CP_COMMIT();
    };

    issue(0, 0);
    if (NT > 1) issue(1, 1);
    float acc[2][4][4] = {};
    for (int kt = 0; kt < NT; ++kt) {
        int s = kt % GSTG;
        if (kt + 1 < NT) CP_WAIT1(); else CP_WAIT0();
        __syncthreads();
        const __half* Asb = As + s * A_STAGE;
        const __half* Bsb = Bs + s * B_STAGE;
        #pragma unroll
        for (int ks = 0; ks < 2; ++ks) {
            const int k16 = ks * 16;
            uint32_t af[2][4], bf[2][4];
            #pragma unroll
            for (int mt = 0; mt < 2; ++mt)
                LDSM4(af[mt], smem_u32(Asb + (wm + mt * 16 + lrow) * HST + k16 + lcolA));
            #pragma unroll
            for (int np = 0; np < 2; ++np)
                LDSM4T(bf[np], smem_u32(Bsb + (k16 + lrow) * BNST + wn + np * 16 + lcolA));
            #pragma unroll
            for (int mt = 0; mt < 2; ++mt)
                #pragma unroll
                for (int np = 0; np < 2; ++np) {
                    mma_h(acc[mt][np * 2 + 0], af[mt][0], af[mt][1], af[mt][2], af[mt][3],
                          bf[np][0], bf[np][1]);
                    mma_h(acc[mt][np * 2 + 1], af[mt][0], af[mt][1], af[mt][2], af[mt][3],
                          bf[np][2], bf[np][3]);
                }
        }
        if (kt + 2 < NT) issue(kt + 2, (kt + 2) % GSTG);
    }

    #pragma unroll
    for (int mt = 0; mt < 2; ++mt) {
        #pragma unroll
        for (int nt = 0; nt < 4; ++nt) {
            int row = m0 + wm + mt * 16 + g;
            int col = n0 + wn + nt * 8 + 2 * c;
            float2 bb = *(const float2*)&bias[col];
            #pragma unroll
            for (int hh = 0; hh < 2; ++hh) {
                size_t idx = (size_t)(row + hh * 8) * N + col;
                float v0 = acc[mt][nt][hh * 2 + 0] + bb.x;
                float v1 = acc[mt][nt][hh * 2 + 1] + bb.y;
                if (EPI == 1) {
                    float2 rr = *(const float2*)&R[idx];
                    float2 o = {v0 + rr.x, v1 + rr.y};
                    *(float2*)&((float*)Cv)[idx] = o;
                } else {
                    if (EPI == 2) { v0 = gelu_exact(v0); v1 = gelu_exact(v1); }
                    __half2 o = __halves2half2(__float2half_rn(v0), __float2half_rn(v1));
                    *(__half2*)&((__half*)Cv)[idx] = o;
                }
            }
        }
    }
}

// ---------------------------------------------------------------------------
// Fused attention: scores + softmax + attn-map write + PV, 16 q-rows per CTA.
// Phase 1: 8 warps x 16 keys. Phase 3 (PV): warp = d-group x key-half,
// partials reduced through smem. 105.5 KB smem -> 2 CTAs/SM.
// ---------------------------------------------------------------------------
#define SMST 1036
#define SMSTH (2 * SMST)
#define QST  72
#define SC_SMEM (16*SMST*4 + 16*QST*2 + 2*128*QST*2)   // 105472

__global__ void attn_fused(const __half* __restrict__ qkv, float* __restrict__ S,
                           __half* __restrict__ O) {
    extern __shared__ char smraw[];
    float*  Sm = (float*)smraw;
    __half* SmH = (__half*)smraw;
    __half* Qs = (__half*)(smraw + 16 * SMST * 4);
    __half* KV = Qs + 16 * QST;
    const int t = threadIdx.x;
    const int w = t >> 5, lane = t & 31, g = lane >> 2, c = lane & 3;
    const int bh = blockIdx.y, b = bh / HEADS, h = bh % HEADS;
    const int m0 = blockIdx.x * 16;
    const int wn16 = w * 16;
    const int dg  = (w & 3) * 16;
    const int kh  = w >> 2;
    const __half* Qb = qkv + ((size_t)b * NSEQ + m0) * (3 * DIM_) + h * HDIM;
    const __half* Kb = qkv + ((size_t)b * NSEQ) * (3 * DIM_) + DIM_ + h * HDIM;
    const __half* Vb = qkv + ((size_t)b * NSEQ) * (3 * DIM_) + 2 * DIM_ + h * HDIM;
    const int lrow = lane & 15;
    const int lcolA = (lane >> 4) * 8;
    const int browB = (lane >> 4) * 8 + (lane & 7);
    const int bcolB = lane & 8;

    if (t < 128) {
        int row = t >> 3, ch = t & 7;
        CP16(smem_u32(&Qs[row * QST + ch * 8]),
             Qb + (size_t)row * (3 * DIM_) + ch * 8);
    }
    CP_COMMIT();

    auto issueKV = [&](const __half* base, int chn, int buf) {
        __half* Kd = KV + buf * 128 * QST;
        const __half* Kg = base + (size_t)(chn * 128) * (3 * DIM_);
        #pragma unroll
        for (int i = 0; i < 4; ++i) {
            int li = t + i * 256;
            int key = li >> 3, ch = li & 7;
            CP16(smem_u32(&Kd[key * QST + ch * 8]),
                 Kg + (size_t)key * (3 * DIM_) + ch * 8);
        }
        CP_COMMIT();
    };
    issueKV(Kb, 0, 0);
    CP_WAIT0();
    __syncthreads();

    uint32_t aq[4][4];
    #pragma unroll
    for (int ks = 0; ks < 4; ++ks)
        LDSM4(aq[ks], smem_u32(&Qs[lrow * QST + ks * 16 + lcolA]));

    // ---- Phase 1: scores ----
    for (int chn = 0; chn < 8; ++chn) {
        int buf = chn & 1;
        if (chn + 1 < 8) { issueKV(Kb, chn + 1, buf ^ 1); CP_WAIT1(); }
        else             { CP_WAIT0(); }
        __syncthreads();
        const __half* Kc = KV + buf * 128 * QST;
        float acc[2][4] = {};
        #pragma unroll
        for (int ks = 0; ks < 4; ++ks) {
            uint32_t bf[4];
            LDSM4(bf, smem_u32(&Kc[(wn16 + browB) * QST + ks * 16 + bcolB]));
            mma_h(acc[0], aq[ks][0], aq[ks][1], aq[ks][2], aq[ks][3], bf[0], bf[1]);
            mma_h(acc[1], aq[ks][0], aq[ks][1], aq[ks][2], aq[ks][3], bf[2], bf[3]);
        }
        const float scl = 0.125f;
        #pragma unroll
        for (int nt = 0; nt < 2; ++nt) {
            int colb = chn * 128 + wn16 + nt * 8 + 2 * c;
            float2 o0 = {acc[nt][0] * scl, acc[nt][1] * scl};
            float2 o1 = {acc[nt][2] * scl, acc[nt][3] * scl};
            *(float2*)&Sm[g * SMST + colb]       = o0;
            *(float2*)&Sm[(g + 8) * SMST + colb] = o1;
        }
        __syncthreads();
    }

    issueKV(Vb, 0, 0);
    issueKV(Vb, 1, 1);

    // ---- Phase 2: softmax; fp32 map + half P in place ----
    #pragma unroll
    for (int i = 0; i < 2; ++i) {
        int r = w * 2 + i;
        const float* rowp = Sm + r * SMST;
        __half* hrow = SmH + r * SMSTH;
        float4 v[8];
        float mx = -INFINITY;
        #pragma unroll
        for (int j = 0; j < 8; ++j) {
            v[j] = *(const float4*)(rowp + lane * 4 + j * 128);
            mx = fmaxf(mx, fmaxf(fmaxf(v[j].x, v[j].y), fmaxf(v[j].z, v[j].w)));
        }
        #pragma unroll
        for (int o = 16; o; o >>= 1) mx = fmaxf(mx, __shfl_xor_sync(0xffffffffu, mx, o));
        float s = 0.f;
        #pragma unroll
        for (int j = 0; j < 8; ++j) {
            v[j].x = __expf(v[j].x - mx); v[j].y = __expf(v[j].y - mx);
            v[j].z = __expf(v[j].z - mx); v[j].w = __expf(v[j].w - mx);
            s += v[j].x + v[j].y + v[j].z + v[j].w;
        }
        #pragma unroll
        for (int o = 16; o; o >>= 1) s += __shfl_xor_sync(0xffffffffu, s, o);
        float inv = 1.0f / s;
        float* outp = S + ((size_t)bh * NSEQ + m0 + r) * NSEQ + lane * 4;
        #pragma unroll
        for (int j = 0; j < 8; ++j) {
            float4 o = {v[j].x * inv, v[j].y * inv, v[j].z * inv, v[j].w * inv};
            *(float4*)(outp + j * 128) = o;
            __half2 h0 = __floats2half2_rn(o.x, o.y);
            __half2 h1 = __floats2half2_rn(o.z, o.w);
            uint2 hp = {h2_u32(h0), h2_u32(h1)};
            *(uint2*)(hrow + lane * 4 + j * 128) = hp;
        }
    }

    // ---- Phase 3: PV (warp = 16 rows x 16 d-cols over its 64-key half) ----
    float acc2[2][4] = {};
    for (int chn = 0; chn < 8; ++chn) {
        int buf = chn & 1;
        if (chn + 2 < 8) CP_WAIT1(); else CP_WAIT0();
        __syncthreads();
        const __half* Vc = KV + buf * 128 * QST;
        #pragma unroll
        for (int ks = 0; ks < 4; ++ks) {
            const int kk = kh * 64 + ks * 16;
            uint32_t pf[4], vf[4];
            LDSM4(pf, smem_u32(&SmH[lrow * SMSTH + chn * 128 + kk + lcolA]));
            LDSM4T(vf, smem_u32(&Vc[(kk + lrow) * QST + dg + lcolA]));
            mma_h(acc2[0], pf[0], pf[1], pf[2], pf[3], vf[0], vf[1]);
            mma_h(acc2[1], pf[0], pf[1], pf[2], pf[3], vf[2], vf[3]);
        }
        __syncthreads();
        if (chn + 2 < 8) issueKV(Vb, chn + 2, buf);
    }

    // Reduce key halves via Sm (free now).
    __syncthreads();
    float* red = Sm;
    if (kh == 1) {
        float* dst = red + ((w & 3) * 32 + lane) * 8;
        #pragma unroll
        for (int nt = 0; nt < 2; ++nt)
            #pragma unroll
            for (int i = 0; i < 4; ++i) dst[nt * 4 + i] = acc2[nt][i];
    }
    __syncthreads();
    if (kh == 0) {
        const float* src = red + ((w & 3) * 32 + lane) * 8;
        #pragma unroll
        for (int nt = 0; nt < 2; ++nt)
            #pragma unroll
            for (int i = 0; i < 4; ++i) acc2[nt][i] += src[nt * 4 + i];
        #pragma unroll
        for (int nt = 0; nt < 2; ++nt) {
            int col = dg + nt * 8 + 2 * c;
            #pragma unroll
            for (int hh = 0; hh < 2; ++hh) {
                int row = m0 + g + hh * 8;
                size_t idx = ((size_t)b * NSEQ + row) * DIM_ + h * HDIM + col;
                __half2 o = __halves2half2(__float2half_rn(acc2[nt][hh * 2 + 0]),
                                           __float2half_rn(acc2[nt][hh * 2 + 1]));
                *(__half2*)&O[idx] = o;
            }
        }
    }
}

// ---------------------------------------------------------------------------
// Host orchestration
// ---------------------------------------------------------------------------
extern "C" void kernel_launch(void* const* d_in, const int* in_sizes, int n_in,
                              void* d_out, int out_size) {
    (void)in_sizes; (void)n_in; (void)out_size;
    const float* x = (const float*)d_in[0];
    const float* prm[24];
    for (int i = 0; i < 24; ++i) prm[i] = (const float*)d_in[1 + i];
    // per-layer: 0 qkv_w, 1 qkv_b, 2 proj_w, 3 proj_b, 4 ln1_g, 5 ln1_b,
    //            6 ln2_g, 7 ln2_b, 8 mlp_w1, 9 mlp_b1, 10 mlp_w2, 11 mlp_b2

    float* out   = (float*)d_out;
    float* attn0 = out + OUT_ELEMS;
    float* attn1 = attn0 + ATTN_ELEMS;

    __half *p_ln, *p_qkv, *p_ao, *p_h, *p_wc;
    float *p_x1, *p_x2, *p_x3;
    cudaGetSymbolAddress((void**)&p_ln,  g_ln);
    cudaGetSymbolAddress((void**)&p_qkv, g_qkv);
    cudaGetSymbolAddress((void**)&p_ao,  g_ao);
    cudaGetSymbolAddress((void**)&p_h,   g_h);
    cudaGetSymbolAddress((void**)&p_x1,  g_x1);
    cudaGetSymbolAddress((void**)&p_x2,  g_x2);
    cudaGetSymbolAddress((void**)&p_x3,  g_x3);
    cudaGetSymbolAddress((void**)&p_wc,  g_wc);

    cudaFuncSetAttribute(attn_fused,
                         cudaFuncAttributeMaxDynamicSharedMemorySize, SC_SMEM);
    cudaFuncSetAttribute(gemm_h<0>, cudaFuncAttributeMaxDynamicSharedMemorySize, GEMM_SMEM);
    cudaFuncSetAttribute(gemm_h<1>, cudaFuncAttributeMaxDynamicSharedMemorySize, GEMM_SMEM);
    cudaFuncSetAttribute(gemm_h<2>, cudaFuncAttributeMaxDynamicSharedMemorySize, GEMM_SMEM);

    dim3 blk(256);

    const int QKV_N = DIM_ * 3 * DIM_;
    const int PRJ_N = DIM_ * DIM_;
    const int W1_N  = DIM_ * MLPH;
    __half* wq[2]; __half* wp[2]; __half* w1[2]; __half* w2[2];
    for (int L = 0; L < 2; ++L) {
        __half* base = p_wc + (size_t)L * WL_STRIDE;
        wq[L] = base;
        wp[L] = base + QKV_N;
        w1[L] = base + QKV_N + PRJ_N;
        w2[L] = base + QKV_N + PRJ_N + W1_N;
    }
    // single conversion launch for both layers (13824 blocks)
    conv_w8<<<2 * WL_STRIDE / 1024, blk>>>(
        prm[0], prm[2], prm[8], prm[10],
        prm[12 + 0], prm[12 + 2], prm[12 + 8], prm[12 + 10], p_wc);

    auto attention = [&](int L, const float* xin, float* attnbuf, float* xout) {
        const float* const* p = prm + L * 12;
        ln_kernel<<<MROWS, blk>>>(xin, p[4], p[5], p_ln);
        gemm_h<0><<<dim3(3 * DIM_ / 64, MROWS / 128), blk, GEMM_SMEM>>>(
            p_ln, wq[L], p[1], nullptr, p_qkv, MROWS, 3 * DIM_, DIM_);
        attn_fused<<<dim3(NSEQ / 16, 48), blk, SC_SMEM>>>(p_qkv, attnbuf, p_ao);
        gemm_h<1><<<dim3(DIM_ / 64, MROWS / 128), blk, GEMM_SMEM>>>(
            p_ao, wp[L], p[3], xin, xout, MROWS, DIM_, DIM_);
    };
    auto mlp_tail = [&](int L, const __half* lnin, const float* resid, float* xout) {
        const float* const* p = prm + L * 12;
        gemm_h<2><<<dim3(MLPH / 64, MROWS / 128), blk, GEMM_SMEM>>>(
            lnin, w1[L], p[9], nullptr, p_h, MROWS, MLPH, DIM_);
        gemm_h<1><<<dim3(DIM_ / 64, MROWS / 128), blk, GEMM_SMEM>>>(
            p_h, w2[L], p[11], resid, xout, MROWS, DIM_, MLPH);
    };

    attention(0, x,    attn0, p_x1);
    attention(1, p_x1, attn1, p_x2);
    ln_kernel<<<MROWS, blk>>>(p_x2, prm[12 + 6], prm[12 + 7], p_ln);
    mlp_tail(1, p_ln, p_x2, p_x3);
    ln_blend_kernel<<<MROWS, blk>>>(p_x1, p_x3, prm[6], prm[7], p_ln, p_x2);
    mlp_tail(0, p_ln, p_x2, out);
}